// round 2
// baseline (speedup 1.0000x reference)
#include <cuda_runtime.h>
#include <math.h>

// Problem constants
#define SEQ   1000
#define IND   100
#define POOLW 10
#define HID   64
#define OUTD  5
#define NB    16
#define BATCH 65536

// Tiling: 64 batch rows per CTA; 128 threads; thread t -> row (t&63), out-half (t>>6)
#define BM     64
#define KC     64             // k-chunk = 4 i's x 16 basis
#define NCHUNK 25             // 1600 / 64
#define NTHR   128

// smem (floats):
//   xp  [100][64]   offset 0     (6400)  -- reused for c2s (5120) in phase 3
//   sA  [64][68]    offset 6400  (4352)  -- reused for reduction scratch in phase 3
#define OFF_XP 0
#define OFF_SA 6400
#define SMEM_FLOATS (6400 + 64*68)
#define SMEM_BYTES  (SMEM_FLOATS * 4)

__device__ __forceinline__ unsigned long long pk2(float lo, float hi) {
    unsigned long long r;
    asm("mov.b64 %0, {%1,%2};" : "=l"(r) : "f"(lo), "f"(hi));
    return r;
}
__device__ __forceinline__ void upk2(unsigned long long v, float& lo, float& hi) {
    asm("mov.b64 {%0,%1}, %2;" : "=f"(lo), "=f"(hi) : "l"(v));
}
__device__ __forceinline__ void fma2(unsigned long long& d, unsigned long long a, unsigned long long b) {
    asm("fma.rn.f32x2 %0, %1, %2, %0;" : "+l"(d) : "l"(a), "l"(b));
}

extern __shared__ float smem[];

__global__ __launch_bounds__(NTHR, 3)
void kan_fused_kernel(const float* __restrict__ x,
                      const float* __restrict__ c1,    // [64][100][16] = [64][1600]
                      const float* __restrict__ c2,    // [5][64][16]   = [5][1024]
                      const float* __restrict__ centers,
                      float* __restrict__ out)         // [BATCH][5]
{
    const int t   = threadIdx.x;
    const int blk = blockIdx.x;

    float* xp  = smem + OFF_XP;   // [i][row]
    float* sA  = smem + OFF_SA;   // [k][o], pad 68
    float* c2s = smem + OFF_XP;   // phase 3: flat copy of c2 (5120 floats)
    float* red = smem + OFF_SA;   // phase 3: reduction scratch

    const float K2 = -0.5f / 0.36f;

    float ctr[NB];
    #pragma unroll
    for (int n = 0; n < NB; n++) ctr[n] = __ldg(centers + n);

    // ---------------- Phase 1: pool 1000 -> 100 ----------------
    const float* xblk = x + (size_t)blk * BM * SEQ;
    for (int p = t; p < BM * IND; p += NTHR) {
        int row = p / IND;
        int i   = p - row * IND;
        const float* xr = xblk + row * SEQ + i * POOLW;
        float s = 0.f;
        #pragma unroll
        for (int m = 0; m < POOLW; m++) s += __ldg(xr + m);
        xp[i * BM + row] = s * (1.0f / POOLW);
    }
    __syncthreads();

    const int r  = t & 63;   // batch row within CTA
    const int oh = t >> 6;   // output half: o in [32*oh, 32*oh+32)

    // per-row stats (two-pass, ddof=1, eps outside sqrt) — pair does it redundantly
    float mu = 0.f;
    #pragma unroll 10
    for (int i = 0; i < IND; i++) mu += xp[i * BM + r];
    mu *= (1.0f / IND);
    float var = 0.f;
    #pragma unroll 10
    for (int i = 0; i < IND; i++) { float d = xp[i * BM + r] - mu; var += d * d; }
    var *= (1.0f / (IND - 1));
    const float sc = 1.0f / (sqrtf(var) + 1e-6f);

    // ---------------- Phase 2: basis (registers) + GEMM1 with broadcast A ----------------
    unsigned long long acc[16];
    #pragma unroll
    for (int m = 0; m < 16; m++) acc[m] = 0ull;

    for (int ch = 0; ch < NCHUNK; ch++) {
        __syncthreads();   // previous chunk's sA reads complete

        // stage sA[k][o] = c1[o][ch*64 + k]  (coalesced along k across lanes)
        {
            int k  = t & 63;
            int o0 = t >> 6;               // 0 or 1
            const float* cp = c1 + (size_t)ch * KC + k;
            #pragma unroll 8
            for (int j = 0; j < 32; j++) {
                int o = o0 + 2 * j;
                sA[k * 68 + o] = __ldg(cp + (size_t)o * 1600);
            }
        }
        __syncthreads();

        #pragma unroll 1
        for (int ii = 0; ii < 4; ii++) {
            float xn = (xp[(ch * 4 + ii) * BM + r] - mu) * sc;
            float br[NB];
            #pragma unroll
            for (int n = 0; n < NB; n++) {
                float d = xn - ctr[n];
                br[n] = __expf(K2 * d * d);
            }
            #pragma unroll 4
            for (int n = 0; n < NB; n++) {
                unsigned long long b2 = pk2(br[n], br[n]);
                const ulonglong2* ar =
                    (const ulonglong2*)(sA + (ii * NB + n) * 68 + oh * 32);
                #pragma unroll
                for (int j = 0; j < 8; j++) {
                    ulonglong2 a = ar[j];           // broadcast LDS.128 (all lanes same addr)
                    fma2(acc[2 * j],     b2, a.x);
                    fma2(acc[2 * j + 1], b2, a.y);
                }
            }
        }
    }

    // ---------------- epilogue: tanh into registers ----------------
    float h[32];
    #pragma unroll
    for (int m = 0; m < 16; m++) upk2(acc[m], h[2 * m], h[2 * m + 1]);
    #pragma unroll 8
    for (int j = 0; j < 32; j++) h[j] = tanhf(h[j]);

    __syncthreads();   // all sA/xp reads done before reuse

    // pair-exchange stats for row norm over 64 values
    float ps = 0.f, pq = 0.f;
    #pragma unroll 8
    for (int j = 0; j < 32; j++) { ps += h[j]; pq += h[j] * h[j]; }
    red[t * 2]     = ps;
    red[t * 2 + 1] = pq;

    // stage c2 into smem (xp region is dead now)
    for (int e = t; e < OUTD * HID * NB; e += NTHR) c2s[e] = __ldg(c2 + e);
    __syncthreads();

    float sm = red[(t ^ 64) * 2]     + ps;
    float sq = red[(t ^ 64) * 2 + 1] + pq;
    float m2 = sm * (1.0f / HID);
    float v2 = (sq - (float)HID * m2 * m2) * (1.0f / (HID - 1));
    const float s2 = 1.0f / (sqrtf(v2) + 1e-6f);

    // ---------------- Phase 3: basis2 + GEMM2 on this thread's 32 h's ----------------
    float oacc[OUTD] = {0.f, 0.f, 0.f, 0.f, 0.f};
    #pragma unroll 4
    for (int j = 0; j < 32; j++) {
        float xn = (h[j] - m2) * s2;
        int jj = oh * 32 + j;
        #pragma unroll
        for (int n = 0; n < NB; n++) {
            float d = xn - ctr[n];
            float e = __expf(K2 * d * d);
            #pragma unroll
            for (int q = 0; q < OUTD; q++)
                oacc[q] += e * c2s[q * (HID * NB) + jj * NB + n];  // broadcast read
        }
    }

    // combine pair partials
    float* part = red + 2 * NTHR;   // [128][5]
    #pragma unroll
    for (int q = 0; q < OUTD; q++) part[t * 5 + q] = oacc[q];
    __syncthreads();
    if (t < BM) {
        float* op = out + ((size_t)blk * BM + t) * OUTD;
        #pragma unroll
        for (int q = 0; q < OUTD; q++)
            op[q] = part[t * 5 + q] + part[(t + 64) * 5 + q];
    }
}

extern "C" void kernel_launch(void* const* d_in, const int* in_sizes, int n_in,
                              void* d_out, int out_size)
{
    const float* x       = (const float*)d_in[0];   // [65536,1000]
    const float* c1      = (const float*)d_in[1];   // [64,100,16]
    const float* c2      = (const float*)d_in[2];   // [5,64,16]
    const float* centers = (const float*)d_in[3];   // [16]
    float* out = (float*)d_out;

    cudaFuncSetAttribute(kan_fused_kernel,
                         cudaFuncAttributeMaxDynamicSharedMemorySize, SMEM_BYTES);
    kan_fused_kernel<<<BATCH / BM, NTHR, SMEM_BYTES>>>(x, c1, c2, centers, out);
}